// round 16
// baseline (speedup 1.0000x reference)
#include <cuda_runtime.h>
#include <math.h>

#define MAXN 50000
#define MAXE 400000
#define NREL 200
#define CHUNK 256
#define CHUNK2 128
#define MAXB 4096
#define SCHUNK 1024
#define HB 148            // histogram blocks appended to loop1 grid

typedef unsigned long long ull;

// Scratch (static device globals — no allocation allowed)
__device__ __align__(16) float g_tmp1[MAXN * 64];
__device__ __align__(16) float g_h1[MAXN * 64];
__device__ __align__(16) float g_tmp2[MAXN * 128];

// sort scratch (g_hist/g_cursor start zero; k_scan re-zeroes them each launch)
__device__ int g_hist[NREL];
__device__ int g_cursor[NREL];
__device__ int g_offs[NREL + 1];
__device__ int g_bpre[NREL + 1];    // block offsets for CHUNK (edge1)
__device__ int g_bpre2[NREL + 1];   // block offsets for CHUNK2 (edge2)
__device__ int g_blockrel[MAXB];
__device__ int g_blockrel2[MAXB];
__device__ __align__(16) int4 g_edge_s[MAXE];   // {src_hid, dst, norm_bits, 0}

// ---------------------------------------------------------------------------
// f32x2 packed-math helpers
// ---------------------------------------------------------------------------
__device__ __forceinline__ ull pack2(float x, float y) {
    ull r; asm("mov.b64 %0, {%1,%2};" : "=l"(r) : "f"(x), "f"(y)); return r;
}
__device__ __forceinline__ void unpack2(ull v, float& x, float& y) {
    asm("mov.b64 {%0,%1}, %2;" : "=f"(x), "=f"(y) : "l"(v));
}
__device__ __forceinline__ void fma2(ull& acc, ull a, ull b) {
    asm("fma.rn.f32x2 %0, %1, %2, %0;" : "+l"(acc) : "l"(a), "l"(b));
}
__device__ __forceinline__ void mul2(ull& a, ull b) {
    asm("mul.rn.f32x2 %0, %1, %2;" : "+l"(a) : "l"(a), "l"(b));
}
__device__ __forceinline__ void red4(float* addr, float a, float b, float c, float d) {
    asm volatile("red.global.add.v4.f32 [%0], {%1,%2,%3,%4};"
                 :: "l"(addr), "f"(a), "f"(b), "f"(c), "f"(d) : "memory");
}

// ---------------------------------------------------------------------------
// Fused loop1 + histogram.
// ---------------------------------------------------------------------------
__global__ void __launch_bounds__(256, 5) k_loop1h(
        const float* __restrict__ emb,
        const int* __restrict__ h_ids,
        const float* __restrict__ W,
        const float* __restrict__ b1,
        int n,
        const int* __restrict__ rel,
        int ne,
        int nb1) {
    __shared__ ull Xd[64][64];         // 32 KB : Xd[k][node] = (x,x)
    int tid = threadIdx.x;

    if ((int)blockIdx.x >= nb1) {
        int* sh = (int*)Xd;
        for (int i = tid; i < NREL; i += 256) sh[i] = 0;
        __syncthreads();
        int hb = blockIdx.x - nb1;
        int stride = HB * 256;
        for (int e = hb * 256 + tid; e < ne; e += stride)
            atomicAdd(&sh[rel[e]], 1);
        __syncthreads();
        for (int i = tid; i < NREL; i += 256)
            if (sh[i]) atomicAdd(&g_hist[i], sh[i]);
        return;
    }

    int base = blockIdx.x * 64;
    {
        int nl = tid & 63;
        int kq = tid >> 6;
        int node = base + nl;
        float4 v[4];
        if (node < n) {
            const float4* s = (const float4*)(emb + (size_t)h_ids[node] * 64 + kq * 16);
#pragma unroll
            for (int j = 0; j < 4; j++) v[j] = s[j];
        } else {
#pragma unroll
            for (int j = 0; j < 4; j++) v[j] = make_float4(0.f, 0.f, 0.f, 0.f);
        }
#pragma unroll
        for (int j = 0; j < 4; j++) {
            Xd[kq * 16 + j * 4 + 0][nl] = pack2(v[j].x, v[j].x);
            Xd[kq * 16 + j * 4 + 1][nl] = pack2(v[j].y, v[j].y);
            Xd[kq * 16 + j * 4 + 2][nl] = pack2(v[j].z, v[j].z);
            Xd[kq * 16 + j * 4 + 3][nl] = pack2(v[j].w, v[j].w);
        }
    }
    __syncthreads();

    int ty = tid >> 4, tx = tid & 15;
    int n0 = ty * 4, c0 = tx * 4;
    ull acc[4][2];
    {
        ulonglong2 bb = *(const ulonglong2*)&b1[c0];
#pragma unroll
        for (int i = 0; i < 4; i++) { acc[i][0] = bb.x; acc[i][1] = bb.y; }
    }

#pragma unroll 8
    for (int k = 0; k < 64; k++) {
        ulonglong2 xa = *(const ulonglong2*)&Xd[k][n0];
        ulonglong2 xb = *(const ulonglong2*)&Xd[k][n0 + 2];
        ulonglong2 wv = *(const ulonglong2*)(W + k * 64 + c0);
        fma2(acc[0][0], xa.x, wv.x); fma2(acc[0][1], xa.x, wv.y);
        fma2(acc[1][0], xa.y, wv.x); fma2(acc[1][1], xa.y, wv.y);
        fma2(acc[2][0], xb.x, wv.x); fma2(acc[2][1], xb.x, wv.y);
        fma2(acc[3][0], xb.y, wv.x); fma2(acc[3][1], xb.y, wv.y);
    }
#pragma unroll
    for (int i = 0; i < 4; i++) {
        int node = base + n0 + i;
        if (node < n) {
            float4 o;
            unpack2(acc[i][0], o.x, o.y);
            unpack2(acc[i][1], o.z, o.w);
            *(float4*)&g_tmp1[(size_t)node * 64 + c0] = o;
        }
    }
}

// ---------------------------------------------------------------------------
// Scan: offs/bpre/bpre2, reset hist+cursor, fill BOTH blockrel tables.
// ---------------------------------------------------------------------------
__global__ void k_scan() {
    __shared__ int sh[256], sb[256], sc[256];
    int t = threadIdx.x;
    int h = (t < NREL) ? g_hist[t] : 0;
    if (t < NREL) { g_hist[t] = 0; g_cursor[t] = 0; }
    int b = (h + CHUNK - 1) / CHUNK;
    int c = (h + CHUNK2 - 1) / CHUNK2;
    sh[t] = h; sb[t] = b; sc[t] = c;
    __syncthreads();
    for (int off = 1; off < 256; off <<= 1) {
        int vh = 0, vb = 0, vc = 0;
        if (t >= off) { vh = sh[t - off]; vb = sb[t - off]; vc = sc[t - off]; }
        __syncthreads();
        sh[t] += vh; sb[t] += vb; sc[t] += vc;
        __syncthreads();
    }
    if (t < NREL) {
        g_offs[t + 1] = sh[t];
        g_bpre[t + 1] = sb[t];
        g_bpre2[t + 1] = sc[t];
    }
    if (t == 0) { g_offs[0] = 0; g_bpre[0] = 0; g_bpre2[0] = 0; }
    __syncthreads();
    int totalB = sb[NREL - 1];
    for (int blk = t; blk < totalB; blk += 256) {
        int lo = 0, hi = NREL - 1;
        while (lo < hi) {
            int mid = (lo + hi) >> 1;
            if (sb[mid] > blk) hi = mid; else lo = mid + 1;
        }
        int prev = lo ? sb[lo - 1] : 0;
        g_blockrel[blk] = (lo << 16) | (blk - prev);
    }
    int totalC = sc[NREL - 1];
    for (int blk = t; blk < totalC; blk += 256) {
        int lo = 0, hi = NREL - 1;
        while (lo < hi) {
            int mid = (lo + hi) >> 1;
            if (sc[mid] > blk) hi = mid; else lo = mid + 1;
        }
        int prev = lo ? sc[lo - 1] : 0;
        g_blockrel2[blk] = (lo << 16) | (blk - prev);
    }
}

// ---------------------------------------------------------------------------
__global__ void k_scatter(const int* __restrict__ rel,
                          const int* __restrict__ src,
                          const int* __restrict__ dst,
                          const float* __restrict__ norm,
                          const int* __restrict__ h_ids,
                          int ne) {
    __shared__ int cur[NREL];
    __shared__ int base[NREL];
    for (int i = threadIdx.x; i < NREL; i += 256) cur[i] = 0;
    __syncthreads();
    int start = blockIdx.x * SCHUNK;
    int lr[4], lrank[4];
#pragma unroll
    for (int it = 0; it < 4; it++) {
        int e = start + it * 256 + threadIdx.x;
        if (e < ne) {
            int r = rel[e];
            lr[it] = r;
            lrank[it] = atomicAdd(&cur[r], 1);
        }
    }
    __syncthreads();
    for (int i = threadIdx.x; i < NREL; i += 256) {
        int c = cur[i];
        base[i] = c ? atomicAdd(&g_cursor[i], c) : 0;
    }
    __syncthreads();
#pragma unroll
    for (int it = 0; it < 4; it++) {
        int e = start + it * 256 + threadIdx.x;
        if (e < ne) {
            int r = lr[it];
            int pos = g_offs[r] + base[r] + lrank[it];
            int4 rec;
            rec.x = h_ids[src[e]];
            rec.y = dst[e];
            rec.z = __float_as_int(norm[e]);
            rec.w = 0;
            g_edge_s[pos] = rec;
        }
    }
}

// ---------------------------------------------------------------------------
// Layer-1 edges (CHUNK=256, FIXED 16 iterations). 16 threads/edge,
// 16-ull register weights, red4, direct x LDG with 1-deep prefetch.
// ---------------------------------------------------------------------------
__global__ void __launch_bounds__(256, 4) k_edge1s(const float* __restrict__ emb,
                                                   const float* __restrict__ w1) {
    if ((int)blockIdx.x >= g_bpre[NREL]) return;
    int info = g_blockrel[blockIdx.x];
    int r = info >> 16, ci = info & 0xFFFF;
    int ebase = g_offs[r] + ci * CHUNK;
    int cnt = min(CHUNK, g_offs[r + 1] - ebase);

    __shared__ __align__(16) int4 sedge[CHUNK];

    int tid = threadIdx.x;
    int u = tid & 15;
    int es = (tid >> 4) & 1;
    int w = tid >> 5;
    int b = u >> 1, q = u & 1;

    const float4* wrow = (const float4*)(w1 + (size_t)r * 512 + b * 64 + q * 4);
    ull wlo[8], whi[8];
#pragma unroll
    for (int i = 0; i < 8; i++) {
        float4 w4 = wrow[i * 2];
        wlo[i] = pack2(w4.x, w4.y);
        whi[i] = pack2(w4.z, w4.w);
    }

    if (tid < cnt) sedge[tid] = g_edge_s[ebase + tid];
    __syncthreads();

    int jc = w * 2 + es;
    bool vc = (jc < cnt);
    int4 rc = vc ? sedge[jc] : make_int4(0, 0, 0, 0);
    const float4* xp = (const float4*)(emb + (size_t)rc.x * 64 + b * 8);
    float4 xA = xp[0], xB = xp[1];

    for (int it = 0; it < 16; it++) {
        int jn = jc + 16;
        bool vn = (jn < cnt);
        int4 rn = vn ? sedge[jn] : make_int4(0, 0, 0, 0);
        const float4* xq = (const float4*)(emb + (size_t)rn.x * 64 + b * 8);
        float4 yA = xq[0], yB = xq[1];

        if (vc) {
            float nm = __int_as_float(rc.z);
            ull a0 = 0ULL, a1 = 0ULL;
            ull xx;
            xx = pack2(xA.x, xA.x); fma2(a0, xx, wlo[0]); fma2(a1, xx, whi[0]);
            xx = pack2(xA.y, xA.y); fma2(a0, xx, wlo[1]); fma2(a1, xx, whi[1]);
            xx = pack2(xA.z, xA.z); fma2(a0, xx, wlo[2]); fma2(a1, xx, whi[2]);
            xx = pack2(xA.w, xA.w); fma2(a0, xx, wlo[3]); fma2(a1, xx, whi[3]);
            xx = pack2(xB.x, xB.x); fma2(a0, xx, wlo[4]); fma2(a1, xx, whi[4]);
            xx = pack2(xB.y, xB.y); fma2(a0, xx, wlo[5]); fma2(a1, xx, whi[5]);
            xx = pack2(xB.z, xB.z); fma2(a0, xx, wlo[6]); fma2(a1, xx, whi[6]);
            xx = pack2(xB.w, xB.w); fma2(a0, xx, wlo[7]); fma2(a1, xx, whi[7]);
            ull nn = pack2(nm, nm);
            mul2(a0, nn); mul2(a1, nn);
            float f0, f1, f2, f3;
            unpack2(a0, f0, f1);
            unpack2(a1, f2, f3);
            red4(&g_tmp1[(size_t)rc.y * 64 + b * 8 + q * 4], f0, f1, f2, f3);
        }
        xA = yA; xB = yB; jc = jn; vc = vn; rc = rn;
    }
}

// ---------------------------------------------------------------------------
// h1 = relu(tmp1); tmp2 = b2 + h1 @ loop_w2 (64x128). Zero-MOV f32x2 GEMM.
// ---------------------------------------------------------------------------
__global__ void __launch_bounds__(256, 5) k_loop2(const float* __restrict__ W2,
                                                  const float* __restrict__ b2,
                                                  int n) {
    __shared__ ull Xd[64][32];         // 16 KB : Xd[k][node] = (h,h)
    int tid = threadIdx.x;
    int base = blockIdx.x * 32;
    {
        int nl = tid & 31;
        int kq = tid >> 5;
        int node = base + nl;
        float4 v[2];
        if (node < n) {
            const float4* s = (const float4*)(g_tmp1 + (size_t)node * 64 + kq * 8);
            v[0] = s[0]; v[1] = s[1];
            v[0].x = fmaxf(v[0].x, 0.f); v[0].y = fmaxf(v[0].y, 0.f);
            v[0].z = fmaxf(v[0].z, 0.f); v[0].w = fmaxf(v[0].w, 0.f);
            v[1].x = fmaxf(v[1].x, 0.f); v[1].y = fmaxf(v[1].y, 0.f);
            v[1].z = fmaxf(v[1].z, 0.f); v[1].w = fmaxf(v[1].w, 0.f);
            float4* d = (float4*)(g_h1 + (size_t)node * 64 + kq * 8);
            d[0] = v[0]; d[1] = v[1];
        } else {
            v[0] = make_float4(0.f, 0.f, 0.f, 0.f);
            v[1] = v[0];
        }
#pragma unroll
        for (int j = 0; j < 2; j++) {
            Xd[kq * 8 + j * 4 + 0][nl] = pack2(v[j].x, v[j].x);
            Xd[kq * 8 + j * 4 + 1][nl] = pack2(v[j].y, v[j].y);
            Xd[kq * 8 + j * 4 + 2][nl] = pack2(v[j].z, v[j].z);
            Xd[kq * 8 + j * 4 + 3][nl] = pack2(v[j].w, v[j].w);
        }
    }
    __syncthreads();

    int ty = tid >> 5, tx = tid & 31;
    int n0 = ty * 4, c0 = tx * 4;
    ull acc[4][2];
    {
        ulonglong2 bb = *(const ulonglong2*)&b2[c0];
#pragma unroll
        for (int i = 0; i < 4; i++) { acc[i][0] = bb.x; acc[i][1] = bb.y; }
    }

#pragma unroll 8
    for (int k = 0; k < 64; k++) {
        ulonglong2 xa = *(const ulonglong2*)&Xd[k][n0];
        ulonglong2 xb = *(const ulonglong2*)&Xd[k][n0 + 2];
        ulonglong2 wv = *(const ulonglong2*)(W2 + k * 128 + c0);
        fma2(acc[0][0], xa.x, wv.x); fma2(acc[0][1], xa.x, wv.y);
        fma2(acc[1][0], xa.y, wv.x); fma2(acc[1][1], xa.y, wv.y);
        fma2(acc[2][0], xb.x, wv.x); fma2(acc[2][1], xb.x, wv.y);
        fma2(acc[3][0], xb.y, wv.x); fma2(acc[3][1], xb.y, wv.y);
    }
#pragma unroll
    for (int i = 0; i < 4; i++) {
        int node = base + n0 + i;
        if (node < n) {
            float4 o;
            unpack2(acc[i][0], o.x, o.y);
            unpack2(acc[i][1], o.z, o.w);
            *(float4*)&g_tmp2[(size_t)node * 128 + c0] = o;
        }
    }
}

// ---------------------------------------------------------------------------
// Layer-2 edges (CHUNK2=128, FIXED 16 iterations). Warp per edge, 16-ull
// register weights, red4, x from g_h1, 1-deep prefetch. NO reg cap.
// ---------------------------------------------------------------------------
__global__ void __launch_bounds__(256) k_edge2s(const float* __restrict__ w2) {
    if ((int)blockIdx.x >= g_bpre2[NREL]) return;
    int info = g_blockrel2[blockIdx.x];
    int r = info >> 16, ci = info & 0xFFFF;
    int ebase = g_offs[r] + ci * CHUNK2;
    int cnt = min(CHUNK2, g_offs[r + 1] - ebase);

    __shared__ __align__(16) int4 sedge[CHUNK2];

    int tid = threadIdx.x;
    int w = tid >> 5, t = tid & 31;
    int b = t >> 2, q = t & 3;

    const float* wp = w2 + (size_t)r * 1024 + b * 128 + q * 4;
    ull wlo[8], whi[8];
#pragma unroll
    for (int i = 0; i < 8; i++) {
        float4 w4 = *(const float4*)(wp + i * 16);
        wlo[i] = pack2(w4.x, w4.y);
        whi[i] = pack2(w4.z, w4.w);
    }

    if (tid < cnt) sedge[tid] = g_edge_s[ebase + tid];
    __syncthreads();

    int jc = w;
    bool vc = (jc < cnt);
    int4 rc = vc ? sedge[jc] : make_int4(0, 0, 0, 0);
    const float4* xp = (const float4*)(g_h1 + (size_t)rc.x * 64 + b * 8);
    float4 xA = xp[0], xB = xp[1];

    for (int it = 0; it < 16; it++) {
        int jn = jc + 8;
        bool vn = (jn < cnt);
        int4 rn = vn ? sedge[jn] : make_int4(0, 0, 0, 0);
        const float4* xq = (const float4*)(g_h1 + (size_t)rn.x * 64 + b * 8);
        float4 yA = xq[0], yB = xq[1];

        if (vc) {
            float nm = __int_as_float(rc.z);
            ull a0 = 0ULL, a1 = 0ULL;
            ull xx;
            xx = pack2(xA.x, xA.x); fma2(a0, xx, wlo[0]); fma2(a1, xx, whi[0]);
            xx = pack2(xA.y, xA.y); fma2(a0, xx, wlo[1]); fma2(a1, xx, whi[1]);
            xx = pack2(xA.z, xA.z); fma2(a0, xx, wlo[2]); fma2(a1, xx, whi[2]);
            xx = pack2(xA.w, xA.w); fma2(a0, xx, wlo[3]); fma2(a1, xx, whi[3]);
            xx = pack2(xB.x, xB.x); fma2(a0, xx, wlo[4]); fma2(a1, xx, whi[4]);
            xx = pack2(xB.y, xB.y); fma2(a0, xx, wlo[5]); fma2(a1, xx, whi[5]);
            xx = pack2(xB.z, xB.z); fma2(a0, xx, wlo[6]); fma2(a1, xx, whi[6]);
            xx = pack2(xB.w, xB.w); fma2(a0, xx, wlo[7]); fma2(a1, xx, whi[7]);
            ull nn = pack2(nm, nm);
            mul2(a0, nn); mul2(a1, nn);
            float f0, f1, f2, f3;
            unpack2(a0, f0, f1);
            unpack2(a1, f2, f3);
            red4(&g_tmp2[(size_t)rc.y * 128 + b * 16 + q * 4], f0, f1, f2, f3);
        }
        xA = yA; xB = yB; jc = jn; vc = vn; rc = rn;
    }
}

// ---------------------------------------------------------------------------
// Final: out = m + sqrt(softplus(raw_v)+1e-8) * eps   (float4 vectorized)
// ---------------------------------------------------------------------------
__global__ void k_final(const float* __restrict__ eps,
                        float* __restrict__ out,
                        int n) {
    int gi = blockIdx.x * blockDim.x + threadIdx.x;
    int total = n * 16;
    if (gi < total) {
        int node = gi >> 4, c4 = gi & 15;
        const float4* t2 = (const float4*)g_tmp2;
        float4 m = t2[(size_t)node * 32 + c4];
        float4 rv = t2[(size_t)node * 32 + 16 + c4];
        float4 e = ((const float4*)eps)[gi];
        float4 o;
        float sp;
        sp = (rv.x > 20.f) ? rv.x : log1pf(expf(rv.x)); o.x = m.x + sqrtf(sp + 1e-8f) * e.x;
        sp = (rv.y > 20.f) ? rv.y : log1pf(expf(rv.y)); o.y = m.y + sqrtf(sp + 1e-8f) * e.y;
        sp = (rv.z > 20.f) ? rv.z : log1pf(expf(rv.z)); o.z = m.z + sqrtf(sp + 1e-8f) * e.z;
        sp = (rv.w > 20.f) ? rv.w : log1pf(expf(rv.w)); o.w = m.w + sqrtf(sp + 1e-8f) * e.w;
        ((float4*)out)[gi] = o;
    }
}

// ---------------------------------------------------------------------------
extern "C" void kernel_launch(void* const* d_in, const int* in_sizes, int n_in,
                              void* d_out, int out_size) {
    const float* emb   = (const float*)d_in[0];
    const float* norm  = (const float*)d_in[1];
    const float* eps   = (const float*)d_in[2];
    const float* w1    = (const float*)d_in[3];
    const float* lw1   = (const float*)d_in[4];
    const float* b1    = (const float*)d_in[5];
    const float* w2    = (const float*)d_in[6];
    const float* lw2   = (const float*)d_in[7];
    const float* b2    = (const float*)d_in[8];
    const int*   h_ids = (const int*)d_in[9];
    const int*   src   = (const int*)d_in[10];
    const int*   dst   = (const int*)d_in[11];
    const int*   rel   = (const int*)d_in[12];

    int n  = in_sizes[9];
    int ne = in_sizes[10];

    int maxb  = ne / CHUNK + NREL + 1;
    int maxb2 = ne / CHUNK2 + NREL + 1;
    int sblocks = (ne + SCHUNK - 1) / SCHUNK;
    int nb1 = (n + 63) / 64;

    k_loop1h<<<nb1 + HB, 256>>>(emb, h_ids, lw1, b1, n, rel, ne, nb1);
    k_scan<<<1, 256>>>();
    k_scatter<<<sblocks, 256>>>(rel, src, dst, norm, h_ids, ne);

    k_edge1s<<<maxb, 256>>>(emb, w1);
    k_loop2<<<(n + 31) / 32, 256>>>(lw2, b2, n);
    k_edge2s<<<maxb2, 256>>>(w2);
    k_final<<<(n * 16 + 255) / 256, 256>>>(eps, (float*)d_out, n);
}

// round 17
// speedup vs baseline: 1.0843x; 1.0843x over previous
#include <cuda_runtime.h>
#include <math.h>

#define MAXN 50000
#define MAXE 400000
#define NREL 200
#define CHUNK 256
#define MAXB 4096
#define SCHUNK 1024
#define HB 148            // histogram blocks appended to loop1 grid

typedef unsigned long long ull;

// Scratch (static device globals — no allocation allowed)
__device__ __align__(16) float g_tmp1[MAXN * 64];
__device__ __align__(16) float g_tmp2[MAXN * 128];

// sort scratch (g_hist/g_cursor start zero; k_scan re-zeroes them each launch)
__device__ int g_hist[NREL];
__device__ int g_cursor[NREL];
__device__ int g_offs[NREL + 1];
__device__ int g_bpre[NREL + 1];
__device__ int g_blockrel[MAXB];
__device__ __align__(16) int4 g_edge_s[MAXE];   // {src_hid, dst, norm_bits, 0}

// ---------------------------------------------------------------------------
// f32x2 packed-math helpers
// ---------------------------------------------------------------------------
__device__ __forceinline__ ull pack2(float x, float y) {
    ull r; asm("mov.b64 %0, {%1,%2};" : "=l"(r) : "f"(x), "f"(y)); return r;
}
__device__ __forceinline__ void unpack2(ull v, float& x, float& y) {
    asm("mov.b64 {%0,%1}, %2;" : "=f"(x), "=f"(y) : "l"(v));
}
__device__ __forceinline__ void fma2(ull& acc, ull a, ull b) {
    asm("fma.rn.f32x2 %0, %1, %2, %0;" : "+l"(acc) : "l"(a), "l"(b));
}
__device__ __forceinline__ void mul2(ull& a, ull b) {
    asm("mul.rn.f32x2 %0, %1, %2;" : "+l"(a) : "l"(a), "l"(b));
}
__device__ __forceinline__ void red4(float* addr, float a, float b, float c, float d) {
    asm volatile("red.global.add.v4.f32 [%0], {%1,%2,%3,%4};"
                 :: "l"(addr), "f"(a), "f"(b), "f"(c), "f"(d) : "memory");
}

// ---------------------------------------------------------------------------
// Fused loop1 + histogram.
// ---------------------------------------------------------------------------
__global__ void __launch_bounds__(256, 5) k_loop1h(
        const float* __restrict__ emb,
        const int* __restrict__ h_ids,
        const float* __restrict__ W,
        const float* __restrict__ b1,
        int n,
        const int* __restrict__ rel,
        int ne,
        int nb1) {
    __shared__ ull Xd[64][64];         // 32 KB : Xd[k][node] = (x,x)
    int tid = threadIdx.x;

    if ((int)blockIdx.x >= nb1) {
        int* sh = (int*)Xd;
        for (int i = tid; i < NREL; i += 256) sh[i] = 0;
        __syncthreads();
        int hb = blockIdx.x - nb1;
        int stride = HB * 256;
        for (int e = hb * 256 + tid; e < ne; e += stride)
            atomicAdd(&sh[rel[e]], 1);
        __syncthreads();
        for (int i = tid; i < NREL; i += 256)
            if (sh[i]) atomicAdd(&g_hist[i], sh[i]);
        return;
    }

    int base = blockIdx.x * 64;
    {
        int nl = tid & 63;
        int kq = tid >> 6;
        int node = base + nl;
        float4 v[4];
        if (node < n) {
            const float4* s = (const float4*)(emb + (size_t)h_ids[node] * 64 + kq * 16);
#pragma unroll
            for (int j = 0; j < 4; j++) v[j] = s[j];
        } else {
#pragma unroll
            for (int j = 0; j < 4; j++) v[j] = make_float4(0.f, 0.f, 0.f, 0.f);
        }
#pragma unroll
        for (int j = 0; j < 4; j++) {
            Xd[kq * 16 + j * 4 + 0][nl] = pack2(v[j].x, v[j].x);
            Xd[kq * 16 + j * 4 + 1][nl] = pack2(v[j].y, v[j].y);
            Xd[kq * 16 + j * 4 + 2][nl] = pack2(v[j].z, v[j].z);
            Xd[kq * 16 + j * 4 + 3][nl] = pack2(v[j].w, v[j].w);
        }
    }
    __syncthreads();

    int ty = tid >> 4, tx = tid & 15;
    int n0 = ty * 4, c0 = tx * 4;
    ull acc[4][2];
    {
        ulonglong2 bb = *(const ulonglong2*)&b1[c0];
#pragma unroll
        for (int i = 0; i < 4; i++) { acc[i][0] = bb.x; acc[i][1] = bb.y; }
    }

#pragma unroll 8
    for (int k = 0; k < 64; k++) {
        ulonglong2 xa = *(const ulonglong2*)&Xd[k][n0];
        ulonglong2 xb = *(const ulonglong2*)&Xd[k][n0 + 2];
        ulonglong2 wv = *(const ulonglong2*)(W + k * 64 + c0);
        fma2(acc[0][0], xa.x, wv.x); fma2(acc[0][1], xa.x, wv.y);
        fma2(acc[1][0], xa.y, wv.x); fma2(acc[1][1], xa.y, wv.y);
        fma2(acc[2][0], xb.x, wv.x); fma2(acc[2][1], xb.x, wv.y);
        fma2(acc[3][0], xb.y, wv.x); fma2(acc[3][1], xb.y, wv.y);
    }
#pragma unroll
    for (int i = 0; i < 4; i++) {
        int node = base + n0 + i;
        if (node < n) {
            float4 o;
            unpack2(acc[i][0], o.x, o.y);
            unpack2(acc[i][1], o.z, o.w);
            *(float4*)&g_tmp1[(size_t)node * 64 + c0] = o;
        }
    }
}

// ---------------------------------------------------------------------------
__global__ void k_scan() {
    __shared__ int sh[256], sb[256];
    int t = threadIdx.x;
    int h = (t < NREL) ? g_hist[t] : 0;
    if (t < NREL) { g_hist[t] = 0; g_cursor[t] = 0; }
    int b = (h + CHUNK - 1) / CHUNK;
    sh[t] = h; sb[t] = b;
    __syncthreads();
    for (int off = 1; off < 256; off <<= 1) {
        int vh = 0, vb = 0;
        if (t >= off) { vh = sh[t - off]; vb = sb[t - off]; }
        __syncthreads();
        sh[t] += vh; sb[t] += vb;
        __syncthreads();
    }
    if (t < NREL) { g_offs[t + 1] = sh[t]; g_bpre[t + 1] = sb[t]; }
    if (t == 0) { g_offs[0] = 0; g_bpre[0] = 0; }
    __syncthreads();
    int totalB = sb[NREL - 1];
    for (int blk = t; blk < totalB; blk += 256) {
        int lo = 0, hi = NREL - 1;
        while (lo < hi) {
            int mid = (lo + hi) >> 1;
            if (sb[mid] > blk) hi = mid; else lo = mid + 1;
        }
        int prev = lo ? sb[lo - 1] : 0;
        g_blockrel[blk] = (lo << 16) | (blk - prev);
    }
}

// ---------------------------------------------------------------------------
__global__ void k_scatter(const int* __restrict__ rel,
                          const int* __restrict__ src,
                          const int* __restrict__ dst,
                          const float* __restrict__ norm,
                          const int* __restrict__ h_ids,
                          int ne) {
    __shared__ int cur[NREL];
    __shared__ int base[NREL];
    for (int i = threadIdx.x; i < NREL; i += 256) cur[i] = 0;
    __syncthreads();
    int start = blockIdx.x * SCHUNK;
    int lr[4], lrank[4];
#pragma unroll
    for (int it = 0; it < 4; it++) {
        int e = start + it * 256 + threadIdx.x;
        if (e < ne) {
            int r = rel[e];
            lr[it] = r;
            lrank[it] = atomicAdd(&cur[r], 1);
        }
    }
    __syncthreads();
    for (int i = threadIdx.x; i < NREL; i += 256) {
        int c = cur[i];
        base[i] = c ? atomicAdd(&g_cursor[i], c) : 0;
    }
    __syncthreads();
#pragma unroll
    for (int it = 0; it < 4; it++) {
        int e = start + it * 256 + threadIdx.x;
        if (e < ne) {
            int r = lr[it];
            int pos = g_offs[r] + base[r] + lrank[it];
            int4 rec;
            rec.x = h_ids[src[e]];
            rec.y = dst[e];
            rec.z = __float_as_int(norm[e]);
            rec.w = 0;
            g_edge_s[pos] = rec;
        }
    }
}

// ---------------------------------------------------------------------------
// Layer-1 edges (CHUNK=256, FIXED 16 iterations). 16 threads/edge,
// 16-ull register weights, red4, direct x LDG with 1-deep prefetch.
// ---------------------------------------------------------------------------
__global__ void __launch_bounds__(256, 4) k_edge1s(const float* __restrict__ emb,
                                                   const float* __restrict__ w1) {
    if ((int)blockIdx.x >= g_bpre[NREL]) return;
    int info = g_blockrel[blockIdx.x];
    int r = info >> 16, ci = info & 0xFFFF;
    int ebase = g_offs[r] + ci * CHUNK;
    int cnt = min(CHUNK, g_offs[r + 1] - ebase);

    __shared__ __align__(16) int4 sedge[CHUNK];

    int tid = threadIdx.x;
    int u = tid & 15;
    int es = (tid >> 4) & 1;
    int w = tid >> 5;
    int b = u >> 1, q = u & 1;

    const float4* wrow = (const float4*)(w1 + (size_t)r * 512 + b * 64 + q * 4);
    ull wlo[8], whi[8];
#pragma unroll
    for (int i = 0; i < 8; i++) {
        float4 w4 = wrow[i * 2];
        wlo[i] = pack2(w4.x, w4.y);
        whi[i] = pack2(w4.z, w4.w);
    }

    if (tid < cnt) sedge[tid] = g_edge_s[ebase + tid];
    __syncthreads();

    int jc = w * 2 + es;
    bool vc = (jc < cnt);
    int4 rc = vc ? sedge[jc] : make_int4(0, 0, 0, 0);
    const float4* xp = (const float4*)(emb + (size_t)rc.x * 64 + b * 8);
    float4 xA = xp[0], xB = xp[1];

    for (int it = 0; it < 16; it++) {
        int jn = jc + 16;
        bool vn = (jn < cnt);
        int4 rn = vn ? sedge[jn] : make_int4(0, 0, 0, 0);
        const float4* xq = (const float4*)(emb + (size_t)rn.x * 64 + b * 8);
        float4 yA = xq[0], yB = xq[1];

        if (vc) {
            float nm = __int_as_float(rc.z);
            ull a0 = 0ULL, a1 = 0ULL;
            ull xx;
            xx = pack2(xA.x, xA.x); fma2(a0, xx, wlo[0]); fma2(a1, xx, whi[0]);
            xx = pack2(xA.y, xA.y); fma2(a0, xx, wlo[1]); fma2(a1, xx, whi[1]);
            xx = pack2(xA.z, xA.z); fma2(a0, xx, wlo[2]); fma2(a1, xx, whi[2]);
            xx = pack2(xA.w, xA.w); fma2(a0, xx, wlo[3]); fma2(a1, xx, whi[3]);
            xx = pack2(xB.x, xB.x); fma2(a0, xx, wlo[4]); fma2(a1, xx, whi[4]);
            xx = pack2(xB.y, xB.y); fma2(a0, xx, wlo[5]); fma2(a1, xx, whi[5]);
            xx = pack2(xB.z, xB.z); fma2(a0, xx, wlo[6]); fma2(a1, xx, whi[6]);
            xx = pack2(xB.w, xB.w); fma2(a0, xx, wlo[7]); fma2(a1, xx, whi[7]);
            ull nn = pack2(nm, nm);
            mul2(a0, nn); mul2(a1, nn);
            float f0, f1, f2, f3;
            unpack2(a0, f0, f1);
            unpack2(a1, f2, f3);
            red4(&g_tmp1[(size_t)rc.y * 64 + b * 8 + q * 4], f0, f1, f2, f3);
        }
        xA = yA; xB = yB; jc = jn; vc = vn; rc = rn;
    }
}

// ---------------------------------------------------------------------------
// tmp2 = b2 + relu(tmp1) @ loop_w2 (64x128). Zero-MOV f32x2 GEMM.
// NO g_h1 materialization — edge2 applies relu on the fly.
// ---------------------------------------------------------------------------
__global__ void __launch_bounds__(256, 5) k_loop2(const float* __restrict__ W2,
                                                  const float* __restrict__ b2,
                                                  int n) {
    __shared__ ull Xd[64][32];         // 16 KB : Xd[k][node] = (h,h)
    int tid = threadIdx.x;
    int base = blockIdx.x * 32;
    {
        int nl = tid & 31;
        int kq = tid >> 5;
        int node = base + nl;
        float4 v[2];
        if (node < n) {
            const float4* s = (const float4*)(g_tmp1 + (size_t)node * 64 + kq * 8);
            v[0] = s[0]; v[1] = s[1];
            v[0].x = fmaxf(v[0].x, 0.f); v[0].y = fmaxf(v[0].y, 0.f);
            v[0].z = fmaxf(v[0].z, 0.f); v[0].w = fmaxf(v[0].w, 0.f);
            v[1].x = fmaxf(v[1].x, 0.f); v[1].y = fmaxf(v[1].y, 0.f);
            v[1].z = fmaxf(v[1].z, 0.f); v[1].w = fmaxf(v[1].w, 0.f);
        } else {
            v[0] = make_float4(0.f, 0.f, 0.f, 0.f);
            v[1] = v[0];
        }
#pragma unroll
        for (int j = 0; j < 2; j++) {
            Xd[kq * 8 + j * 4 + 0][nl] = pack2(v[j].x, v[j].x);
            Xd[kq * 8 + j * 4 + 1][nl] = pack2(v[j].y, v[j].y);
            Xd[kq * 8 + j * 4 + 2][nl] = pack2(v[j].z, v[j].z);
            Xd[kq * 8 + j * 4 + 3][nl] = pack2(v[j].w, v[j].w);
        }
    }
    __syncthreads();

    int ty = tid >> 5, tx = tid & 31;
    int n0 = ty * 4, c0 = tx * 4;
    ull acc[4][2];
    {
        ulonglong2 bb = *(const ulonglong2*)&b2[c0];
#pragma unroll
        for (int i = 0; i < 4; i++) { acc[i][0] = bb.x; acc[i][1] = bb.y; }
    }

#pragma unroll 8
    for (int k = 0; k < 64; k++) {
        ulonglong2 xa = *(const ulonglong2*)&Xd[k][n0];
        ulonglong2 xb = *(const ulonglong2*)&Xd[k][n0 + 2];
        ulonglong2 wv = *(const ulonglong2*)(W2 + k * 128 + c0);
        fma2(acc[0][0], xa.x, wv.x); fma2(acc[0][1], xa.x, wv.y);
        fma2(acc[1][0], xa.y, wv.x); fma2(acc[1][1], xa.y, wv.y);
        fma2(acc[2][0], xb.x, wv.x); fma2(acc[2][1], xb.x, wv.y);
        fma2(acc[3][0], xb.y, wv.x); fma2(acc[3][1], xb.y, wv.y);
    }
#pragma unroll
    for (int i = 0; i < 4; i++) {
        int node = base + n0 + i;
        if (node < n) {
            float4 o;
            unpack2(acc[i][0], o.x, o.y);
            unpack2(acc[i][1], o.z, o.w);
            *(float4*)&g_tmp2[(size_t)node * 128 + c0] = o;
        }
    }
}

// ---------------------------------------------------------------------------
// Layer-2 edges (CHUNK=256, FIXED 32 iterations). Warp per edge, 16-ull
// register weights, red4, x from g_tmp1 with in-register relu, 1-deep
// prefetch. NO reg cap.
// ---------------------------------------------------------------------------
__global__ void __launch_bounds__(256) k_edge2s(const float* __restrict__ w2) {
    if ((int)blockIdx.x >= g_bpre[NREL]) return;
    int info = g_blockrel[blockIdx.x];
    int r = info >> 16, ci = info & 0xFFFF;
    int ebase = g_offs[r] + ci * CHUNK;
    int cnt = min(CHUNK, g_offs[r + 1] - ebase);

    __shared__ __align__(16) int4 sedge[CHUNK];

    int tid = threadIdx.x;
    int w = tid >> 5, t = tid & 31;
    int b = t >> 2, q = t & 3;

    const float* wp = w2 + (size_t)r * 1024 + b * 128 + q * 4;
    ull wlo[8], whi[8];
#pragma unroll
    for (int i = 0; i < 8; i++) {
        float4 w4 = *(const float4*)(wp + i * 16);
        wlo[i] = pack2(w4.x, w4.y);
        whi[i] = pack2(w4.z, w4.w);
    }

    if (tid < cnt) sedge[tid] = g_edge_s[ebase + tid];
    __syncthreads();

    int jc = w;
    bool vc = (jc < cnt);
    int4 rc = vc ? sedge[jc] : make_int4(0, 0, 0, 0);
    const float4* xp = (const float4*)(g_tmp1 + (size_t)rc.x * 64 + b * 8);
    float4 xA = xp[0], xB = xp[1];

    for (int it = 0; it < 32; it++) {
        int jn = jc + 8;
        bool vn = (jn < cnt);
        int4 rn = vn ? sedge[jn] : make_int4(0, 0, 0, 0);
        const float4* xq = (const float4*)(g_tmp1 + (size_t)rn.x * 64 + b * 8);
        float4 yA = xq[0], yB = xq[1];

        if (vc) {
            // relu on the fly: h1 = relu(tmp1)
            xA.x = fmaxf(xA.x, 0.f); xA.y = fmaxf(xA.y, 0.f);
            xA.z = fmaxf(xA.z, 0.f); xA.w = fmaxf(xA.w, 0.f);
            xB.x = fmaxf(xB.x, 0.f); xB.y = fmaxf(xB.y, 0.f);
            xB.z = fmaxf(xB.z, 0.f); xB.w = fmaxf(xB.w, 0.f);
            float nm = __int_as_float(rc.z);
            ull a0 = 0ULL, a1 = 0ULL;
            ull xx;
            xx = pack2(xA.x, xA.x); fma2(a0, xx, wlo[0]); fma2(a1, xx, whi[0]);
            xx = pack2(xA.y, xA.y); fma2(a0, xx, wlo[1]); fma2(a1, xx, whi[1]);
            xx = pack2(xA.z, xA.z); fma2(a0, xx, wlo[2]); fma2(a1, xx, whi[2]);
            xx = pack2(xA.w, xA.w); fma2(a0, xx, wlo[3]); fma2(a1, xx, whi[3]);
            xx = pack2(xB.x, xB.x); fma2(a0, xx, wlo[4]); fma2(a1, xx, whi[4]);
            xx = pack2(xB.y, xB.y); fma2(a0, xx, wlo[5]); fma2(a1, xx, whi[5]);
            xx = pack2(xB.z, xB.z); fma2(a0, xx, wlo[6]); fma2(a1, xx, whi[6]);
            xx = pack2(xB.w, xB.w); fma2(a0, xx, wlo[7]); fma2(a1, xx, whi[7]);
            ull nn = pack2(nm, nm);
            mul2(a0, nn); mul2(a1, nn);
            float f0, f1, f2, f3;
            unpack2(a0, f0, f1);
            unpack2(a1, f2, f3);
            red4(&g_tmp2[(size_t)rc.y * 128 + b * 16 + q * 4], f0, f1, f2, f3);
        }
        xA = yA; xB = yB; jc = jn; vc = vn; rc = rn;
    }
}

// ---------------------------------------------------------------------------
// Final: out = m + sqrt(softplus(raw_v)+1e-8) * eps   (float4 vectorized)
// ---------------------------------------------------------------------------
__global__ void k_final(const float* __restrict__ eps,
                        float* __restrict__ out,
                        int n) {
    int gi = blockIdx.x * blockDim.x + threadIdx.x;
    int total = n * 16;
    if (gi < total) {
        int node = gi >> 4, c4 = gi & 15;
        const float4* t2 = (const float4*)g_tmp2;
        float4 m = t2[(size_t)node * 32 + c4];
        float4 rv = t2[(size_t)node * 32 + 16 + c4];
        float4 e = ((const float4*)eps)[gi];
        float4 o;
        float sp;
        sp = (rv.x > 20.f) ? rv.x : log1pf(expf(rv.x)); o.x = m.x + sqrtf(sp + 1e-8f) * e.x;
        sp = (rv.y > 20.f) ? rv.y : log1pf(expf(rv.y)); o.y = m.y + sqrtf(sp + 1e-8f) * e.y;
        sp = (rv.z > 20.f) ? rv.z : log1pf(expf(rv.z)); o.z = m.z + sqrtf(sp + 1e-8f) * e.z;
        sp = (rv.w > 20.f) ? rv.w : log1pf(expf(rv.w)); o.w = m.w + sqrtf(sp + 1e-8f) * e.w;
        ((float4*)out)[gi] = o;
    }
}

// ---------------------------------------------------------------------------
extern "C" void kernel_launch(void* const* d_in, const int* in_sizes, int n_in,
                              void* d_out, int out_size) {
    const float* emb   = (const float*)d_in[0];
    const float* norm  = (const float*)d_in[1];
    const float* eps   = (const float*)d_in[2];
    const float* w1    = (const float*)d_in[3];
    const float* lw1   = (const float*)d_in[4];
    const float* b1    = (const float*)d_in[5];
    const float* w2    = (const float*)d_in[6];
    const float* lw2   = (const float*)d_in[7];
    const float* b2    = (const float*)d_in[8];
    const int*   h_ids = (const int*)d_in[9];
    const int*   src   = (const int*)d_in[10];
    const int*   dst   = (const int*)d_in[11];
    const int*   rel   = (const int*)d_in[12];

    int n  = in_sizes[9];
    int ne = in_sizes[10];

    int maxb = ne / CHUNK + NREL + 1;
    int sblocks = (ne + SCHUNK - 1) / SCHUNK;
    int nb1 = (n + 63) / 64;

    k_loop1h<<<nb1 + HB, 256>>>(emb, h_ids, lw1, b1, n, rel, ne, nb1);
    k_scan<<<1, 256>>>();
    k_scatter<<<sblocks, 256>>>(rel, src, dst, norm, h_ids, ne);

    k_edge1s<<<maxb, 256>>>(emb, w1);
    k_loop2<<<(n + 31) / 32, 256>>>(lw2, b2, n);
    k_edge2s<<<maxb, 256>>>(w2);
    k_final<<<(n * 16 + 255) / 256, 256>>>(eps, (float*)d_out, n);
}